// round 1
// baseline (speedup 1.0000x reference)
#include <cuda_runtime.h>
#include <cuda_bf16.h>
#include <cstdint>

// ---------------------------------------------------------------------------
// MemoryRotaryAttend: RoPE(q,k) + KV-cache splice + full softmax attention.
// Shapes (fixed by dataset): b=4, n=32, s=512, d=128, mem 4096, start=2048.
// ---------------------------------------------------------------------------

#define B        4
#define NH       32
#define NBH      (B*NH)          // 128
#define SEQ      512
#define D        128
#define TMAX     4096
#define HALF_D   64
#define SCALE    0.08838834764831845f   // 1/sqrt(128)

#define BM       64              // queries per block
#define BN       32              // keys per chunk
#define THREADS  256

// -------- scratch (allocation-free: __device__ globals) --------------------
__device__ float g_Qr[(size_t)NBH * SEQ * D];            //  33.5 MB (rope'd, pre-scaled)
__device__ float g_Kf[(size_t)NBH * TMAX * D];           // 256 MB
__device__ float g_Vf[(size_t)NBH * TMAX * D];           // 256 MB
__device__ float g_cos[SEQ * HALF_D];
__device__ float g_sin[SEQ * HALF_D];

// -------- packed f32x2 helpers (sm_103a FFMA2 path) ------------------------
__device__ __forceinline__ void fma2(unsigned long long& d_,
                                     unsigned long long a,
                                     unsigned long long b,
                                     unsigned long long c) {
    asm("fma.rn.f32x2 %0, %1, %2, %3;" : "=l"(d_) : "l"(a), "l"(b), "l"(c));
}
__device__ __forceinline__ void mul2(unsigned long long& d_,
                                     unsigned long long a,
                                     unsigned long long b) {
    asm("mul.rn.f32x2 %0, %1, %2;" : "=l"(d_) : "l"(a), "l"(b));
}
__device__ __forceinline__ void add2(unsigned long long& d_,
                                     unsigned long long a,
                                     unsigned long long b) {
    asm("add.rn.f32x2 %0, %1, %2;" : "=l"(d_) : "l"(a), "l"(b));
}
__device__ __forceinline__ unsigned long long pack2(float x, float y) {
    unsigned long long r;
    asm("mov.b64 %0, {%1, %2};" : "=l"(r) : "f"(x), "f"(y));
    return r;
}
__device__ __forceinline__ float2 unpack2(unsigned long long v) {
    float2 r;
    asm("mov.b64 {%0, %1}, %2;" : "=f"(r.x), "=f"(r.y) : "l"(v));
    return r;
}

// ---------------------------------------------------------------------------
// Kernel 0: RoPE table (512 positions x 64 freqs), double-precision accurate.
// ---------------------------------------------------------------------------
__global__ void rope_table_kernel(const int* __restrict__ sp) {
    int idx = blockIdx.x * blockDim.x + threadIdx.x;
    if (idx >= SEQ * HALF_D) return;
    int sq = idx >> 6;
    int i  = idx & 63;
    double freq = exp(-(double)i * (9.210340371976184 / 64.0)); // 10000^(-i/64)
    double ang  = (double)(*sp + sq) * freq;
    double s, c;
    sincos(ang, &s, &c);
    g_cos[idx] = (float)c;
    g_sin[idx] = (float)s;
}

// ---------------------------------------------------------------------------
// Kernel 1: build contiguous per-(b,h) K_full / V_full and rope'd+scaled Q.
// Row space: [0, 2*NBH*TMAX) = K/V rows, then [.., +NBH*SEQ) = Q rows.
// 4 rows per 256-thread block, 64 threads (float2 pairs) per row.
// ---------------------------------------------------------------------------
__global__ void prep_kernel(const float* __restrict__ q,
                            const float* __restrict__ k,
                            const float* __restrict__ v,
                            const float* __restrict__ mem,
                            const int*   __restrict__ sp) {
    const int start = *sp;
    const int T     = start + SEQ;
    const long long r = (long long)blockIdx.x * 4 + (threadIdx.x >> 6);
    const int p = threadIdx.x & 63;   // pair index 0..63

    const long long KVROWS = 2LL * NBH * TMAX;
    if (r < KVROWS) {
        const int kvsel = (int)(r / ((long long)NBH * TMAX));   // 0 = K, 1 = V
        const int rr    = (int)(r % ((long long)NBH * TMAX));
        const int bh    = rr / TMAX;
        const int t     = rr % TMAX;
        if (t >= T) return;
        float* dst = (kvsel ? g_Vf : g_Kf) + ((size_t)bh * TMAX + t) * D;
        if (t < start) {
            // history copy from mem_kv[kvsel][b][t][h][:]
            const int b = bh >> 5, h = bh & 31;
            const size_t MEMP = (size_t)B * TMAX * NH * D;
            const float* src = mem + (size_t)kvsel * MEMP +
                               (((size_t)b * TMAX + t) * NH + h) * (size_t)D;
            ((float2*)dst)[p] = ((const float2*)src)[p];
        } else {
            const int sq = t - start;
            const float* src = (kvsel ? v : k) + ((size_t)bh * SEQ + sq) * D;
            float2 x = ((const float2*)src)[p];
            if (kvsel == 0) {  // rope K
                float c = g_cos[sq * HALF_D + p];
                float s = g_sin[sq * HALF_D + p];
                float2 o;
                o.x = x.x * c - x.y * s;
                o.y = x.x * s + x.y * c;
                ((float2*)dst)[p] = o;
            } else {
                ((float2*)dst)[p] = x;
            }
        }
    } else {
        const int rq = (int)(r - KVROWS);
        const int bh = rq / SEQ;
        const int sq = rq % SEQ;
        const float* src = q + ((size_t)bh * SEQ + sq) * D;
        float2 x = ((const float2*)src)[p];
        float c = g_cos[sq * HALF_D + p];
        float s = g_sin[sq * HALF_D + p];
        float2 o;
        o.x = (x.x * c - x.y * s) * SCALE;   // fold softmax scale into Q
        o.y = (x.x * s + x.y * c) * SCALE;
        float* dst = g_Qr + ((size_t)bh * SEQ + sq) * D;
        ((float2*)dst)[p] = o;
    }
}

// ---------------------------------------------------------------------------
// Kernel 2: flash attention, fp32 SIMT with packed fma.rn.f32x2.
// Block = (bh, qtile): 64 queries, loop over T keys in chunks of 32.
// Thread (ql, g): query row ql, d-columns [g*32, g*32+32).
// Chunk-rotation (k + 2g) & 7 makes the 4 g-groups hit disjoint bank sets;
// the 8 q-rows per warp are pure broadcast.
// ---------------------------------------------------------------------------
__global__ void __launch_bounds__(THREADS, 2)
attend_kernel(float* __restrict__ out, const int* __restrict__ sp) {
    const int bh  = blockIdx.x;          // 0..127
    const int qt  = blockIdx.y;          // 0..7
    const int T   = *sp + SEQ;
    const int tid = threadIdx.x;
    const int ql  = tid >> 2;            // 0..63
    const int g   = tid & 3;             // 0..3
    const int qrow = qt * BM + ql;

    __shared__ __align__(16) float sKV[2 * BN * D];   // K at 0, V at BN*D

    // ---- load Q fragment (rotated order, pre-scaled by prep) ----
    const unsigned long long* qp = (const unsigned long long*)
        (g_Qr + ((size_t)bh * SEQ + qrow) * D + g * 32);
    unsigned long long qf[16];
#pragma unroll
    for (int kk = 0; kk < 8; kk++) {
        int idx = (kk + 2 * g) & 7;
        qf[2 * kk]     = qp[2 * idx];
        qf[2 * kk + 1] = qp[2 * idx + 1];
    }

    // ---- rotated smem base pointers (imm-offset addressing per (j,k)) ----
    const ulonglong2* kb[8];
#pragma unroll
    for (int kk = 0; kk < 8; kk++) {
        int idx = (kk + 2 * g) & 7;
        kb[kk] = (const ulonglong2*)(sKV + g * 32 + idx * 4);
    }

    unsigned long long oacc[16];
#pragma unroll
    for (int i = 0; i < 16; i++) oacc[i] = 0ULL;   // packed (0f, 0f)
    float m = -1e30f, l = 0.f;

    const float* Kc = g_Kf + (size_t)bh * TMAX * D;
    const float* Vc = g_Vf + (size_t)bh * TMAX * D;

    const int nc = (T + BN - 1) / BN;
    for (int c = 0; c < nc; c++) {
        const int t0 = c * BN;
        // ---- stage K/V chunk (coalesced float4) ----
        {
            const float4* ks  = (const float4*)(Kc + (size_t)t0 * D);
            const float4* vs  = (const float4*)(Vc + (size_t)t0 * D);
            float4*       sk4 = (float4*)sKV;
#pragma unroll
            for (int i = 0; i < 4; i++) {
                sk4[i * 256 + tid]        = ks[i * 256 + tid];
                sk4[1024 + i * 256 + tid] = vs[i * 256 + tid];
            }
        }
        __syncthreads();

        // ---- S = Q K^T for this chunk (each thread: 32-wide partial dots) ----
        float sj[BN];
#pragma unroll
        for (int j = 0; j < BN; j++) {
            unsigned long long a0 = 0ULL, a1 = 0ULL;
#pragma unroll
            for (int kk = 0; kk < 8; kk++) {
                ulonglong2 kv = kb[kk][j * 32];
                fma2(a0, qf[2 * kk],     kv.x, a0);
                fma2(a1, qf[2 * kk + 1], kv.y, a1);
            }
            add2(a0, a0, a1);
            float2 h = unpack2(a0);
            float dsum = h.x + h.y;
            dsum += __shfl_xor_sync(0xffffffffu, dsum, 1);
            dsum += __shfl_xor_sync(0xffffffffu, dsum, 2);
            sj[j] = dsum;   // scale folded into Q
        }
        if (t0 + BN > T) {
#pragma unroll
            for (int j = 0; j < BN; j++)
                if (t0 + j >= T) sj[j] = -1e30f;
        }

        // ---- online softmax update ----
        float mc = sj[0];
#pragma unroll
        for (int j = 1; j < BN; j++) mc = fmaxf(mc, sj[j]);
        const float mnew = fmaxf(m, mc);
        const float sc   = __expf(m - mnew);
        const unsigned long long sc2 = pack2(sc, sc);
#pragma unroll
        for (int i = 0; i < 16; i++) mul2(oacc[i], oacc[i], sc2);
        l *= sc;
#pragma unroll
        for (int j = 0; j < BN; j++) {
            float pv = __expf(sj[j] - mnew);
            sj[j] = pv;
            l += pv;
        }
        m = mnew;

        // ---- O += P V ----
#pragma unroll
        for (int j = 0; j < BN; j++) {
            const unsigned long long pj = pack2(sj[j], sj[j]);
#pragma unroll
            for (int kk = 0; kk < 8; kk++) {
                ulonglong2 vv = kb[kk][j * 32 + 1024];   // +BN*D/4 u64x2
                fma2(oacc[2 * kk],     pj, vv.x, oacc[2 * kk]);
                fma2(oacc[2 * kk + 1], pj, vv.y, oacc[2 * kk + 1]);
            }
        }
        __syncthreads();
    }

    // ---- epilogue: normalize and store (rotated back) ----
    const float r = 1.0f / l;
    const unsigned long long r2 = pack2(r, r);
    float* orow = out + ((size_t)bh * SEQ + qrow) * D + g * 32;
#pragma unroll
    for (int kk = 0; kk < 8; kk++) {
        int idx = (kk + 2 * g) & 7;
        unsigned long long x0, x1;
        mul2(x0, oacc[2 * kk],     r2);
        mul2(x1, oacc[2 * kk + 1], r2);
        *(ulonglong2*)(orow + idx * 4) = make_ulonglong2(x0, x1);
    }
}

// ---------------------------------------------------------------------------
extern "C" void kernel_launch(void* const* d_in, const int* in_sizes, int n_in,
                              void* d_out, int out_size) {
    const float* q   = (const float*)d_in[0];
    const float* k   = (const float*)d_in[1];
    const float* v   = (const float*)d_in[2];
    const float* mem = (const float*)d_in[3];
    const int*   sp  = (const int*)d_in[4];

    // 0) rope table
    rope_table_kernel<<<(SEQ * HALF_D + 255) / 256, 256>>>(sp);

    // 1) materialize K_full / V_full / Q_rope
    const long long totrows = 2LL * NBH * TMAX + (long long)NBH * SEQ; // 1,114,112
    prep_kernel<<<(unsigned)((totrows + 3) / 4), 256>>>(q, k, v, mem, sp);

    // 2) flash attention
    dim3 grid(NBH, SEQ / BM);   // (128, 8)
    attend_kernel<<<grid, THREADS>>>((float*)d_out, sp);
}